// round 13
// baseline (speedup 1.0000x reference)
#include <cuda_runtime.h>
#include <cuda_fp16.h>
#include <cstdint>

#define Bdim 16
#define L 256
#define H 256

typedef unsigned long long ull;

// Scratch (device globals: allocation-free)
__device__ __align__(16) float g_A[Bdim * L * H];      // A[b][q][o] fp32 (= query @ Wq^T)
__device__ __align__(16) ull   g_Cth[Bdim * 64 * 256]; // [b][og][c]: 4 halves = C[c][4og..4og+3] (+bias), fp16
__device__ __align__(16) __half g_ctxh_t[Bdim * H * L]; // [b][h][c] fp16 transposed context

// ---------------- helpers ----------------
__device__ __forceinline__ ull fma2(ull a, ull b, ull c) {
    ull d; asm("fma.rn.f32x2 %0, %1, %2, %3;" : "=l"(d) : "l"(a), "l"(b), "l"(c)); return d;
}
__device__ __forceinline__ ull add2(ull a, ull b) {
    ull d; asm("add.rn.f32x2 %0, %1, %2;" : "=l"(d) : "l"(a), "l"(b)); return d;
}
__device__ __forceinline__ ull pack2(float lo, float hi) {
    ull d; asm("mov.b64 %0, {%1, %2};" : "=l"(d) : "f"(lo), "f"(hi)); return d;
}
__device__ __forceinline__ float2 unpack2(ull a) {
    float2 r; asm("mov.b64 {%0, %1}, %2;" : "=f"(r.x), "=f"(r.y) : "l"(a)); return r;
}
__device__ __forceinline__ float hsum2(ull a) { float2 r = unpack2(a); return r.x + r.y; }

__device__ __forceinline__ __half2 u2h2(unsigned u) { return *reinterpret_cast<__half2*>(&u); }
__device__ __forceinline__ unsigned h2u(__half2 h) { return *reinterpret_cast<unsigned*>(&h); }
__device__ __forceinline__ __half2 h2_lo(ull x) { return u2h2((unsigned)x); }
__device__ __forceinline__ __half2 h2_hi(ull x) { return u2h2((unsigned)(x >> 32)); }
__device__ __forceinline__ __half2 habs_lop(__half2 x) { return u2h2(h2u(x) & 0x7FFF7FFFu); }
__device__ __forceinline__ ull pack_h4(float f0, float f1, float f2, float f3) {
    __half2 a = __floats2half2_rn(f0, f1);
    __half2 b = __floats2half2_rn(f2, f3);
    return ((ull)h2u(b) << 32) | (ull)h2u(a);
}
__device__ __forceinline__ ull flushh(ull f, __half2 h) {
    float2 x = __half22float2(h);
    return add2(f, pack2(x.x, x.y));
}

// m16n8k16 fp16 MMA, fp32 accumulate in-place
__device__ __forceinline__ void mma16816(float* d, unsigned a0, unsigned a1,
                                         unsigned a2, unsigned a3,
                                         unsigned b0, unsigned b1) {
    asm volatile(
        "mma.sync.aligned.m16n8k16.row.col.f32.f16.f16.f32 "
        "{%0,%1,%2,%3}, {%4,%5,%6,%7}, {%8,%9}, {%0,%1,%2,%3};"
        : "+f"(d[0]), "+f"(d[1]), "+f"(d[2]), "+f"(d[3])
        : "r"(a0), "r"(a1), "r"(a2), "r"(a3), "r"(b0), "r"(b1));
}

// ---------------- context transpose + fp16 convert ----------------
// g_ctxh_t[b][h][c] = fp16(context[b][c][h]). Grid (4,4,16), 256 thr.
__global__ __launch_bounds__(256) void cvt_ctx_kernel(const float* __restrict__ ctx)
{
    __shared__ float T[64][65];
    const int b = blockIdx.z;
    const int c0 = blockIdx.x * 64, h0 = blockIdx.y * 64;
    const int tid = threadIdx.x;
    #pragma unroll
    for (int it = 0; it < 8; it++) {
        int i = it * 256 + tid;
        int c = i >> 5, hp = i & 31;
        float2 v = *(const float2*)&ctx[(b * L + c0 + c) * H + h0 + 2 * hp];
        T[c][2 * hp] = v.x;
        T[c][2 * hp + 1] = v.y;
    }
    __syncthreads();
    #pragma unroll
    for (int it = 0; it < 8; it++) {
        int i = it * 256 + tid;
        int h = i >> 5, cp = i & 31;
        __half2 hv = __floats2half2_rn(T[2 * cp][h], T[2 * cp + 1][h]);
        *reinterpret_cast<__half2*>(&g_ctxh_t[((b * H) + h0 + h) * L + c0 + 2 * cp]) = hv;
    }
}

// ---------------- Projection GEMM (HMMA tensor cores, unchanged R12) ----------------
#define XS_STRIDE 72

__global__ __launch_bounds__(256) void proj_kernel(
    const float* __restrict__ query, const float* __restrict__ context,
    const float* __restrict__ W, const float* __restrict__ bias)
{
    __shared__ __align__(16) char smemraw[18688];  // Xs(9216)+Ws(9216) / T(16896) overlay
    __half* Xs = reinterpret_cast<__half*>(smemraw);
    __half* Ws = reinterpret_cast<__half*>(smemraw + 9216);
    float* T = reinterpret_cast<float*>(smemraw);

    const int tid = threadIdx.x;
    const int lane = tid & 31;
    const int w = tid >> 5;
    const int gid = lane >> 2;
    const int tig = lane & 3;
    const int wm = w & 3;
    const int wn = w >> 2;
    const int row0 = blockIdx.x * 64;
    const int n0 = blockIdx.y * 64;
    const int which = blockIdx.z;

    const float* X = which ? context : query;
    const float* Wbase = W + (which ? H : 0);

    float acc[4][4];
    #pragma unroll
    for (int j = 0; j < 4; j++)
        #pragma unroll
        for (int r = 0; r < 4; r++) acc[j][r] = 0.f;

    for (int kc = 0; kc < H; kc += 64) {
        #pragma unroll
        for (int it = 0; it < 8; it++) {
            int i = it * 256 + tid;
            int kp = i & 31, r = i >> 5;
            float2 xv = *(const float2*)&X[(row0 + r) * H + kc + 2 * kp];
            *reinterpret_cast<__half2*>(&Xs[r * XS_STRIDE + 2 * kp]) = __floats2half2_rn(xv.x, xv.y);
            float2 wv = *(const float2*)&Wbase[(n0 + r) * (2 * H) + kc + 2 * kp];
            *reinterpret_cast<__half2*>(&Ws[r * XS_STRIDE + 2 * kp]) = __floats2half2_rn(wv.x, wv.y);
        }
        __syncthreads();

        #pragma unroll
        for (int ks = 0; ks < 4; ks++) {
            const int k0 = ks * 16;
            const int ra = wm * 16 + gid;
            unsigned a0 = *(const unsigned*)&Xs[ra * XS_STRIDE + k0 + 2 * tig];
            unsigned a1 = *(const unsigned*)&Xs[(ra + 8) * XS_STRIDE + k0 + 2 * tig];
            unsigned a2 = *(const unsigned*)&Xs[ra * XS_STRIDE + k0 + 2 * tig + 8];
            unsigned a3 = *(const unsigned*)&Xs[(ra + 8) * XS_STRIDE + k0 + 2 * tig + 8];
            #pragma unroll
            for (int jn = 0; jn < 4; jn++) {
                const int rb = wn * 32 + jn * 8 + gid;
                unsigned b0 = *(const unsigned*)&Ws[rb * XS_STRIDE + k0 + 2 * tig];
                unsigned b1 = *(const unsigned*)&Ws[rb * XS_STRIDE + k0 + 2 * tig + 8];
                mma16816(acc[jn], a0, a1, a2, a3, b0, b1);
            }
        }
        __syncthreads();
    }

    const int mrow = wm * 16 + gid;
    if (which == 0) {
        #pragma unroll
        for (int jn = 0; jn < 4; jn++) {
            const int ncol = n0 + wn * 32 + jn * 8 + tig * 2;
            *(float2*)&g_A[(row0 + mrow) * H + ncol] = make_float2(acc[jn][0], acc[jn][1]);
            *(float2*)&g_A[(row0 + mrow + 8) * H + ncol] = make_float2(acc[jn][2], acc[jn][3]);
        }
    } else {
        #pragma unroll
        for (int jn = 0; jn < 4; jn++) {
            const int ncl = wn * 32 + jn * 8 + tig * 2;
            float2 bv = *(const float2*)&bias[n0 + ncl];
            T[mrow * 66 + ncl] = acc[jn][0] + bv.x;
            T[mrow * 66 + ncl + 1] = acc[jn][1] + bv.y;
            T[(mrow + 8) * 66 + ncl] = acc[jn][2] + bv.x;
            T[(mrow + 8) * 66 + ncl + 1] = acc[jn][3] + bv.y;
        }
        __syncthreads();
        const int b = row0 >> 8;
        const int c0 = row0 & 255;
        #pragma unroll
        for (int it = 0; it < 4; it++) {
            int e = it * 256 + tid;
            int m = e & 63;
            int ogl = e >> 6;
            float f0 = T[m * 66 + 4 * ogl + 0];
            float f1 = T[m * 66 + 4 * ogl + 1];
            float f2 = T[m * 66 + 4 * ogl + 2];
            float f3 = T[m * 66 + 4 * ogl + 3];
            g_Cth[((ull)(b * 64 + (n0 >> 2) + ogl)) * 256 + (c0 + m)] = pack_h4(f0, f1, f2, f3);
        }
    }
}

// ---------------- Fused score + softmax + AV (AV on tensor cores) ----------------
__global__ __launch_bounds__(256, 4) void score_kernel(
    const float* __restrict__ ctx, const int* __restrict__ mask,
    const float* __restrict__ sw, float* __restrict__ attn_out, float* __restrict__ attn)
{
    __shared__ __align__(16) float Aq[8][256];    // fp32 A (sq phase) -> reused as O (AV out)
    __shared__ __align__(16) float S[8][256];
    __shared__ __align__(16) ull Aqh[8][64];      // fp16 A, 4 o per ull
    __shared__ __align__(16) ull vh2[64];         // fp16 0.495*v, 4 o per ull
    __shared__ __align__(16) __half Sh[8][264];   // fp16 attn (MMA B-frags), padded
    __shared__ float sq_s[8], inv_s[8];

    const int tid = threadIdx.x;
    const int lane = tid & 31;
    const int w = tid >> 5;
    const int gid = lane >> 2;
    const int tig = lane & 3;
    const int b = blockIdx.x >> 5;
    const int q0 = (blockIdx.x & 31) << 3;

    if (tid < 64) {
        float4 s4 = *(const float4*)&sw[4 * tid];
        vh2[tid] = pack_h4(0.495f * s4.x, 0.495f * s4.y, 0.495f * s4.z, 0.495f * s4.w);
    }
    #pragma unroll
    for (int it = 0; it < 2; it++) {
        int fi = it * 256 + tid;
        int q = fi >> 6, o = (fi & 63) << 2;
        float4 v4 = *(const float4*)&g_A[(b * L + q0 + q) * H + o];
        *(float4*)&Aq[q][o] = v4;
        Aqh[q][o >> 2] = pack_h4(v4.x, v4.y, v4.z, v4.w);
    }
    __syncthreads();

    // sq[q] = sum_o v[o] * A[q][o]   (fp32; warp w handles q = w)
    {
        float s = 0.f;
        #pragma unroll
        for (int j = 0; j < 8; j++) s += sw[lane + 32 * j] * Aq[w][lane + 32 * j];
        #pragma unroll
        for (int off = 16; off; off >>= 1) s += __shfl_xor_sync(0xffffffffu, s, off);
        if (lane == 0) sq_s[w] = s;
    }

    // ---- fp16 main score loop (R8 form; abs on ALU pipe) ----
    const __half2 hz = __floats2half2_rn(0.f, 0.f);
    __half2 hq01[8], hq23[8];
    ull facc[8];
    #pragma unroll
    for (int q = 0; q < 8; q++) { hq01[q] = hz; hq23[q] = hz; facc[q] = 0ULL; }
    __half2 hl01 = hz, hl23 = hz;
    ull flin = 0ULL;

    const ull* Cb = g_Cth + (ull)b * (64 * 256) + tid;
    ull p0 = Cb[0];
    ull p1 = Cb[256];

    for (int blk = 0; blk < 8; blk++) {
        #pragma unroll
        for (int j = 0; j < 8; j++) {
            const int og = blk * 8 + j;
            ull c4 = p0;
            p0 = p1;
            p1 = Cb[((og + 2) & 63) * 256];
            __half2 c01 = h2_lo(c4), c23 = h2_hi(c4);
            ull v4 = vh2[og];
            __half2 v01 = h2_lo(v4), v23 = h2_hi(v4);
            hl01 = __hfma2(c01, v01, hl01);
            hl23 = __hfma2(c23, v23, hl23);
            #pragma unroll
            for (int q = 0; q < 8; q++) {
                ull a4 = Aqh[q][og];
                __half2 t01 = habs_lop(__hadd2(h2_lo(a4), c01));
                __half2 t23 = habs_lop(__hadd2(h2_hi(a4), c23));
                hq01[q] = __hfma2(t01, v01, hq01[q]);
                hq23[q] = __hfma2(t23, v23, hq23[q]);
            }
        }
        #pragma unroll
        for (int q = 0; q < 8; q++) {
            facc[q] = flushh(facc[q], __hadd2(hq01[q], hq23[q]));
            hq01[q] = hz; hq23[q] = hz;
        }
        flin = flushh(flin, __hadd2(hl01, hl23));
        hl01 = hz; hl23 = hz;
    }
    __syncthreads();   // sq_s ready

    const int mk = mask[b * L + tid];
    const float sc_scaled = hsum2(flin);
    const float NEG_INF = __int_as_float(0xff800000u);
    #pragma unroll
    for (int q = 0; q < 8; q++) {
        float s = 0.505f * sq_s[q] + 1.02020202f * sc_scaled + hsum2(facc[q]);
        if (mk == 0) s = NEG_INF;
        S[q][tid] = s;
    }
    __syncthreads();

    // softmax: warp w reduces row q = w (fp32)
    {
        float m = NEG_INF;
        #pragma unroll
        for (int j = 0; j < 8; j++) m = fmaxf(m, S[w][lane + 32 * j]);
        #pragma unroll
        for (int off = 16; off; off >>= 1) m = fmaxf(m, __shfl_xor_sync(0xffffffffu, m, off));
        float ssum = 0.f;
        #pragma unroll
        for (int j = 0; j < 8; j++) {
            float e = __expf(S[w][lane + 32 * j] - m);
            S[w][lane + 32 * j] = e;
            ssum += e;
        }
        #pragma unroll
        for (int off = 16; off; off >>= 1) ssum += __shfl_xor_sync(0xffffffffu, ssum, off);
        if (lane == 0) inv_s[w] = 1.f / ssum;
    }
    __syncthreads();

    // scale + write attn (fp32) + fp16 copy for MMA B-frags
    #pragma unroll
    for (int q = 0; q < 8; q++) {
        float a = S[q][tid] * inv_s[q];
        Sh[q][tid] = __float2half(a);
        attn[(b * L + q0 + q) * L + tid] = a;
    }
    __syncthreads();

    // ---- AV on tensor cores: out^T = ctx^T @ attn^T ----
    // m=h(16), n=q(8), k=c(16). Warp w owns h in [32w, 32w+32).
    float acc[2][4];
    #pragma unroll
    for (int ht = 0; ht < 2; ht++)
        #pragma unroll
        for (int r = 0; r < 4; r++) acc[ht][r] = 0.f;

    const __half* ctp = g_ctxh_t + ((ull)(b * H) + w * 32) * L;
    #pragma unroll 4
    for (int ks = 0; ks < 16; ks++) {
        const int k0 = ks * 16;
        unsigned bf0 = *(const unsigned*)&Sh[gid][k0 + 2 * tig];
        unsigned bf1 = *(const unsigned*)&Sh[gid][k0 + 2 * tig + 8];
        #pragma unroll
        for (int ht = 0; ht < 2; ht++) {
            const __half* ap = ctp + ht * 16 * L;
            unsigned a0 = *(const unsigned*)&ap[gid * L + k0 + 2 * tig];
            unsigned a1 = *(const unsigned*)&ap[(gid + 8) * L + k0 + 2 * tig];
            unsigned a2 = *(const unsigned*)&ap[gid * L + k0 + 2 * tig + 8];
            unsigned a3 = *(const unsigned*)&ap[(gid + 8) * L + k0 + 2 * tig + 8];
            mma16816(acc[ht], a0, a1, a2, a3, bf0, bf1);
        }
    }

    // fragments -> O (reuse Aq), then coalesced store
    float (*O)[256] = Aq;
    #pragma unroll
    for (int ht = 0; ht < 2; ht++) {
        int h = w * 32 + ht * 16 + gid;
        O[2 * tig][h] = acc[ht][0];
        O[2 * tig + 1][h] = acc[ht][1];
        O[2 * tig][h + 8] = acc[ht][2];
        O[2 * tig + 1][h + 8] = acc[ht][3];
    }
    __syncthreads();
    #pragma unroll
    for (int q = 0; q < 8; q++) {
        attn_out[(b * L + q0 + q) * H + tid] = O[q][tid];
    }
}

extern "C" void kernel_launch(void* const* d_in, const int* in_sizes, int n_in,
                              void* d_out, int out_size)
{
    const float* query   = (const float*)d_in[0];
    const float* context = (const float*)d_in[1];
    const int*   mask    = (const int*)d_in[2];
    const float* w       = (const float*)d_in[3];
    const float* bias    = (const float*)d_in[4];
    const float* sw      = (const float*)d_in[5];

    float* out = (float*)d_out;
    float* attn_out = out;                      // (B, Lq, H)
    float* attn     = out + Bdim * L * H;       // (B, Lq, Lc)

    dim3 cgrid(4, 4, 16);
    cvt_ctx_kernel<<<cgrid, 256>>>(context);
    dim3 pgrid(64, 4, 2);
    proj_kernel<<<pgrid, 256>>>(query, context, w, bias);
    score_kernel<<<512, 256>>>(context, mask, sw, attn_out, attn);
}